// round 3
// baseline (speedup 1.0000x reference)
#include <cuda_runtime.h>
#include <stdint.h>

// VolumeRenderer: two-pass NeRF (coarse 64 + importance 64 -> fine 128)
// pos @ W is affine in t (pos = ro + rd*t): each sample = FMAs + transcendentals.
// One thread per ray. N derived from inputs; Wd/Wc resolved by size at runtime.

constexpr int NS = 64;          // coarse samples
constexpr int NI = 64;          // importance samples
constexpr int NF = NS + NI;     // fine samples (128)
constexpr float NEARP = 2.0f;
constexpr float FARP  = 6.0f;
constexpr float EPS_W = 1e-5f;
constexpr float EPS_T = 1e-10f;
constexpr float FAR_DIST = 1e10f;

// jax.nn.softplus = logaddexp(x, 0) = max(x,0) + log1p(exp(-|x|))
__device__ __forceinline__ float softplusf(float x) {
    return fmaxf(x, 0.0f) + log1pf(expf(-fabsf(x)));
}

__device__ __forceinline__ float sigmoidf(float x) {
    return 1.0f / (1.0f + expf(-x));   // exp(-x)->inf gives 0: correct limit
}

__global__ __launch_bounds__(256)
void volume_render_kernel(const float* __restrict__ ro_g,
                          const float* __restrict__ rd_g,
                          const float* __restrict__ Wd_g,
                          const float* __restrict__ Wc_g,
                          float* __restrict__ out,
                          int N, long long out_size)
{
    const int ray = blockIdx.x * blockDim.x + threadIdx.x;
    if (ray >= N) return;

    const long long NL = (long long)N;

    const float ro0 = ro_g[ray*3+0], ro1 = ro_g[ray*3+1], ro2 = ro_g[ray*3+2];
    const float rd0 = rd_g[ray*3+0], rd1 = rd_g[ray*3+1], rd2 = rd_g[ray*3+2];

    const float wd0 = __ldg(Wd_g+0), wd1 = __ldg(Wd_g+1), wd2 = __ldg(Wd_g+2);

    // density argument: x(t) = A0 + B0*t
    const float A0 = ro0*wd0 + ro1*wd1 + ro2*wd2;
    const float B0 = rd0*wd0 + rd1*wd1 + rd2*wd2;

    // color arguments: c_j(t) = sigmoid(Ac[j] + Bc[j]*t), Wc row-major [3,3]
    float Ac0, Ac1, Ac2, Bc0, Bc1, Bc2;
    {
        float w00=__ldg(Wc_g+0), w01=__ldg(Wc_g+1), w02=__ldg(Wc_g+2);
        float w10=__ldg(Wc_g+3), w11=__ldg(Wc_g+4), w12=__ldg(Wc_g+5);
        float w20=__ldg(Wc_g+6), w21=__ldg(Wc_g+7), w22=__ldg(Wc_g+8);
        Ac0 = ro0*w00 + ro1*w10 + ro2*w20;
        Ac1 = ro0*w01 + ro1*w11 + ro2*w21;
        Ac2 = ro0*w02 + ro1*w12 + ro2*w22;
        Bc0 = rd0*w00 + rd1*w10 + rd2*w20;
        Bc1 = rd0*w01 + rd1*w11 + rd2*w21;
        Bc2 = rd0*w02 + rd1*w12 + rd2*w22;
    }

    const float STEP = (FARP - NEARP) / 63.0f;   // coarse bin width

    // ---------------- coarse pass ----------------
    float w[NS];
    float trans = 1.0f;
    float r0 = 0.f, r1 = 0.f, r2 = 0.f, depth = 0.f, acc = 0.f, wsum = 0.f;

    #pragma unroll 4
    for (int i = 0; i < NS; i++) {
        float t     = fmaf(STEP, (float)i, NEARP);
        float dens  = softplusf(fmaf(B0, t, A0));
        float dist  = (i < NS-1) ? STEP : FAR_DIST;
        float alpha = 1.0f - expf(-dens * dist);
        float wi    = alpha * trans;
        w[i] = wi;
        r0 = fmaf(wi, sigmoidf(fmaf(Bc0, t, Ac0)), r0);
        r1 = fmaf(wi, sigmoidf(fmaf(Bc1, t, Ac1)), r1);
        r2 = fmaf(wi, sigmoidf(fmaf(Bc2, t, Ac2)), r2);
        depth = fmaf(wi, t, depth);
        acc  += wi;
        wsum += wi + EPS_W;
        trans *= (1.0f - alpha + EPS_T);
    }

    // bounds-guarded section writes (layout: rgb|depth|acc|frgb|fdepth|facc)
    if (3*NL <= out_size) {
        out[(long long)ray*3+0] = r0 + (1.0f - acc);
        out[(long long)ray*3+1] = r1 + (1.0f - acc);
        out[(long long)ray*3+2] = r2 + (1.0f - acc);
    }
    if (4*NL <= out_size) out[3*NL + ray] = depth;
    if (5*NL <= out_size) out[4*NL + ray] = acc;

    // ---------------- inverse-CDF importance sampling ----------------
    // searchsorted(cdf, u, side='right'): idx = first i with cdf[i] > u.
    float ts[NI];
    {
        const float inv_wsum = 1.0f / wsum;
        float cdfb = 0.0f;   // cdf[b]
        int k = 0;
        for (int b = 0; b < NS; b++) {
            float pdf   = (w[b] + EPS_W) * inv_wsum;
            float cdfb1 = cdfb + pdf;                  // cdf[b+1]
            float tb  = fmaf(STEP, (float)b, NEARP);   // t_vals[b]
            int   b1c = (b + 1 < NS) ? (b + 1) : (NS - 1);
            float tb1 = fmaf(STEP, (float)b1c, NEARP); // t_vals[clip(b+1,0,63)]
            while (k < NI) {
                float u = (float)k * (1.0f / 63.0f);
                if (k == NI-1) u = 1.0f;
                if (!(u < cdfb1)) break;               // emit while cdf[b]<=u<cdf[b+1]
                float denom = cdfb1 - cdfb;
                if (denom < EPS_W) denom = 1.0f;
                float frac = (u - cdfb) / denom;
                ts[k] = fmaf(frac, tb1 - tb, tb);
                k++;
            }
            cdfb = cdfb1;
            if (k >= NI) break;
        }
        float tlast = fmaf(STEP, (float)(NS-1), NEARP);
        while (k < NI) ts[k++] = tlast;   // u >= cdf[64] tail -> t[63]
    }

    // ---------------- merge (both streams sorted) ----------------
    float ft[NF];
    {
        int ic = 0, is = 0;
        #pragma unroll 1
        for (int i = 0; i < NF; i++) {
            float tc = (ic < NS) ? fmaf(STEP, (float)ic, NEARP) : 3.0e38f;
            float tv = (is < NI) ? ts[is] : 3.0e38f;
            if (tc <= tv) { ft[i] = tc; ic++; }
            else          { ft[i] = tv; is++; }
        }
    }

    // ---------------- fine pass ----------------
    trans = 1.0f;
    r0 = r1 = r2 = 0.f; depth = 0.f; acc = 0.f;
    float tcur = ft[0];
    #pragma unroll 4
    for (int i = 0; i < NF; i++) {
        float tnext = (i < NF-1) ? ft[i+1] : 0.0f;
        float dist  = (i < NF-1) ? (tnext - tcur) : FAR_DIST;
        float t     = tcur;
        float dens  = softplusf(fmaf(B0, t, A0));
        float alpha = 1.0f - expf(-dens * dist);
        float wi    = alpha * trans;
        r0 = fmaf(wi, sigmoidf(fmaf(Bc0, t, Ac0)), r0);
        r1 = fmaf(wi, sigmoidf(fmaf(Bc1, t, Ac1)), r1);
        r2 = fmaf(wi, sigmoidf(fmaf(Bc2, t, Ac2)), r2);
        depth = fmaf(wi, t, depth);
        acc  += wi;
        trans *= (1.0f - alpha + EPS_T);
        tcur = tnext;
    }

    if (8*NL <= out_size) {
        out[5*NL + (long long)ray*3 + 0] = r0 + (1.0f - acc);
        out[5*NL + (long long)ray*3 + 1] = r1 + (1.0f - acc);
        out[5*NL + (long long)ray*3 + 2] = r2 + (1.0f - acc);
    }
    if (9*NL  <= out_size) out[8*NL + ray] = depth;
    if (10*NL <= out_size) out[9*NL + ray] = acc;
}

extern "C" void kernel_launch(void* const* d_in, const int* in_sizes, int n_in,
                              void* d_out, int out_size)
{
    // Resolve small weight matrices by unique element counts (3 -> Wd, 9 -> Wc).
    // Resolve ro/rd as the first two inputs whose size is 3x the ray count.
    const float* Wd = nullptr;
    const float* Wc = nullptr;
    for (int i = 0; i < n_in; i++) {
        if (in_sizes[i] == 3) Wd = (const float*)d_in[i];
        else if (in_sizes[i] == 9) Wc = (const float*)d_in[i];
    }
    // ray count: prefer out_size/10 (layout has 10 floats per ray), fall back
    // to in_sizes[0]/3.
    int N = (out_size % 10 == 0) ? (out_size / 10) : (in_sizes[0] / 3);

    const float* ro = nullptr;
    const float* rd = nullptr;
    for (int i = 0; i < n_in; i++) {
        if (in_sizes[i] == 3 * N && in_sizes[i] > 9) {
            if (!ro) ro = (const float*)d_in[i];
            else if (!rd) { rd = (const float*)d_in[i]; break; }
        }
    }
    // Fallback to positional order if resolution failed.
    if (!ro || !rd) { ro = (const float*)d_in[0]; rd = (const float*)d_in[1]; }
    if (!Wd) Wd = (const float*)d_in[3];
    if (!Wc) Wc = (const float*)d_in[4];

    float* out = (float*)d_out;
    const int threads = 256;
    const int blocks  = (N + threads - 1) / threads;
    volume_render_kernel<<<blocks, threads>>>(ro, rd, Wd, Wc, out,
                                              N, (long long)out_size);
}

// round 5
// speedup vs baseline: 1.5914x; 1.5914x over previous
#include <cuda_runtime.h>
#include <stdint.h>

// VolumeRenderer: two-pass NeRF (coarse 64 + importance 64 -> fine 128)
// pos @ W is affine in t. One thread per ray. Fused sampler+merge+fine pass
// (no ts/ft arrays). Fast transcendentals with log1p tail preserved.

constexpr int NS = 64;
constexpr int NI = 64;
constexpr float NEARP = 2.0f;
constexpr float FARP  = 6.0f;
constexpr float EPS_W = 1e-5f;
constexpr float EPS_T = 1e-10f;
constexpr float FAR_DIST = 1e10f;

// log1p(e) for e in [0,1]: poly below 0.03 (preserves tiny-density tail that
// caused the R1 7e-2 failure), __logf(1+e) above (rel err <= 2e-6 there).
__device__ __forceinline__ float log1p_fast(float e) {
    float p = e * fmaf(e, fmaf(e, 0.3333333f, -0.5f), 1.0f);
    float l = __logf(1.0f + e);
    return (e < 0.03f) ? p : l;
}

__device__ __forceinline__ float softplus_fast(float x) {
    return fmaxf(x, 0.0f) + log1p_fast(__expf(-fabsf(x)));
}

// sigmoid(x) = 1/(1+exp(-x)); clamp exponent arg so fdividef operand stays
// finite (<2^126) — clamp only changes values where sigmoid < 1e-35.
__device__ __forceinline__ float sigmoid_fast(float x) {
    float e = __expf(fminf(-x, 80.0f));
    return __fdividef(1.0f, 1.0f + e);
}

// exp(a) for a <= 0 (possibly -1e10): clamp for safe hw approx; exp(-87)=1e-38~0
__device__ __forceinline__ float expneg_fast(float a) {
    return __expf(fmaxf(a, -87.0f));
}

__device__ __forceinline__ float clamp80(float y) {
    return fminf(fmaxf(y, -80.0f), 80.0f);
}

__global__ __launch_bounds__(256)
void volume_render_kernel(const float* __restrict__ ro_g,
                          const float* __restrict__ rd_g,
                          const float* __restrict__ Wd_g,
                          const float* __restrict__ Wc_g,
                          float* __restrict__ out,
                          int N, long long out_size)
{
    const int ray = blockIdx.x * blockDim.x + threadIdx.x;
    if (ray >= N) return;

    const long long NL = (long long)N;

    const float ro0 = ro_g[ray*3+0], ro1 = ro_g[ray*3+1], ro2 = ro_g[ray*3+2];
    const float rd0 = rd_g[ray*3+0], rd1 = rd_g[ray*3+1], rd2 = rd_g[ray*3+2];

    const float wd0 = __ldg(Wd_g+0), wd1 = __ldg(Wd_g+1), wd2 = __ldg(Wd_g+2);

    // density argument: x(t) = A0 + B0*t
    const float A0 = ro0*wd0 + ro1*wd1 + ro2*wd2;
    const float B0 = rd0*wd0 + rd1*wd1 + rd2*wd2;

    // color arguments: c_j(t) = sigmoid(Ac[j] + Bc[j]*t), Wc row-major [3,3]
    float Ac0, Ac1, Ac2, Bc0, Bc1, Bc2;
    {
        float w00=__ldg(Wc_g+0), w01=__ldg(Wc_g+1), w02=__ldg(Wc_g+2);
        float w10=__ldg(Wc_g+3), w11=__ldg(Wc_g+4), w12=__ldg(Wc_g+5);
        float w20=__ldg(Wc_g+6), w21=__ldg(Wc_g+7), w22=__ldg(Wc_g+8);
        Ac0 = ro0*w00 + ro1*w10 + ro2*w20;
        Ac1 = ro0*w01 + ro1*w11 + ro2*w21;
        Ac2 = ro0*w02 + ro1*w12 + ro2*w22;
        Bc0 = rd0*w00 + rd1*w10 + rd2*w20;
        Bc1 = rd0*w01 + rd1*w11 + rd2*w21;
        Bc2 = rd0*w02 + rd1*w12 + rd2*w22;
    }

    const float STEP = (FARP - NEARP) / 63.0f;

    // ---------------- coarse pass (uniform grid -> geometric sigmoid recurrences)
    float w[NS];
    float trans = 1.0f;
    float r0 = 0.f, r1 = 0.f, r2 = 0.f, depth = 0.f, acc = 0.f, wsum = 0.f;

    // n_j = exp(-(Ac_j + Bc_j*t)), updated by constant ratio m_j per step.
    // args monotone in t -> inf/0 saturation is absorbing-safe; clamp prologue.
    float n0 = __expf(clamp80(-fmaf(Bc0, NEARP, Ac0)));
    float n1 = __expf(clamp80(-fmaf(Bc1, NEARP, Ac1)));
    float n2 = __expf(clamp80(-fmaf(Bc2, NEARP, Ac2)));
    const float m0 = __expf(-Bc0 * STEP);
    const float m1 = __expf(-Bc1 * STEP);
    const float m2 = __expf(-Bc2 * STEP);

    #pragma unroll 8
    for (int i = 0; i < NS; i++) {
        float t     = fmaf(STEP, (float)i, NEARP);
        float dens  = softplus_fast(fmaf(B0, t, A0));
        float dist  = (i < NS-1) ? STEP : FAR_DIST;
        float alpha = 1.0f - expneg_fast(-dens * dist);
        float wi    = alpha * trans;
        w[i] = wi;
        r0 = fmaf(wi, __fdividef(1.0f, 1.0f + n0), r0);
        r1 = fmaf(wi, __fdividef(1.0f, 1.0f + n1), r1);
        r2 = fmaf(wi, __fdividef(1.0f, 1.0f + n2), r2);
        n0 *= m0; n1 *= m1; n2 *= m2;
        depth = fmaf(wi, t, depth);
        acc  += wi;
        wsum += wi + EPS_W;
        trans *= (1.0f - alpha + EPS_T);
    }

    if (3*NL <= out_size) {
        out[(long long)ray*3+0] = r0 + (1.0f - acc);
        out[(long long)ray*3+1] = r1 + (1.0f - acc);
        out[(long long)ray*3+2] = r2 + (1.0f - acc);
    }
    if (4*NL <= out_size) out[3*NL + ray] = depth;
    if (5*NL <= out_size) out[4*NL + ray] = acc;

    // ---------------- fused importance sampling + merge + fine render ----------
    // Merged sorted stream is exactly: t_0, {imp in bin0}, t_1, {imp in bin1}, ...
    // Render with 1-sample delay: when sample s arrives, render pend with
    // dist = s - pend. Final sample rendered with FAR_DIST.
    float ftr = 1.0f;
    float fr0 = 0.f, fr1 = 0.f, fr2 = 0.f, fdep = 0.f, facc = 0.f;
    float pend = NEARP;                   // first merged sample = t_0

    auto render = [&](float t, float dist) {
        float dens  = softplus_fast(fmaf(B0, t, A0));
        float alpha = 1.0f - expneg_fast(-dens * dist);
        float wi    = alpha * ftr;
        fr0 = fmaf(wi, sigmoid_fast(fmaf(Bc0, t, Ac0)), fr0);
        fr1 = fmaf(wi, sigmoid_fast(fmaf(Bc1, t, Ac1)), fr1);
        fr2 = fmaf(wi, sigmoid_fast(fmaf(Bc2, t, Ac2)), fr2);
        fdep = fmaf(wi, t, fdep);
        facc += wi;
        ftr *= (1.0f - alpha + EPS_T);
    };

    {
        const float inv_wsum = __fdividef(1.0f, wsum);
        float cdfb = 0.0f;
        int k = 0;
        #pragma unroll 1
        for (int b = 0; b < NS; b++) {
            float cdfb1 = cdfb + (w[b] + EPS_W) * inv_wsum;
            float tb    = fmaf(STEP, (float)b, NEARP);
            if (b > 0) { render(pend, tb - pend); pend = tb; }
            float dt    = (b + 1 < NS) ? STEP : 0.0f;     // tb1 - tb (clipped)
            float denom = cdfb1 - cdfb;
            if (denom < EPS_W) denom = 1.0f;
            float rden  = __fdividef(1.0f, denom);
            #pragma unroll 1
            while (k < NI) {
                float u = (k == NI-1) ? 1.0f : (float)k * (1.0f/63.0f);
                if (!(u < cdfb1)) break;
                float s = fmaf((u - cdfb) * rden, dt, tb);
                render(pend, s - pend); pend = s;
                k++;
            }
            cdfb = cdfb1;
        }
        // tail: u >= cdf[64] -> samples at t[63]
        float tlast = fmaf(STEP, (float)(NS-1), NEARP);
        #pragma unroll 1
        while (k < NI) { render(pend, tlast - pend); pend = tlast; k++; }
        render(pend, FAR_DIST);                           // last sample
    }

    if (8*NL <= out_size) {
        out[5*NL + (long long)ray*3 + 0] = fr0 + (1.0f - facc);
        out[5*NL + (long long)ray*3 + 1] = fr1 + (1.0f - facc);
        out[5*NL + (long long)ray*3 + 2] = fr2 + (1.0f - facc);
    }
    if (9*NL  <= out_size) out[8*NL + ray] = fdep;
    if (10*NL <= out_size) out[9*NL + ray] = facc;
}

extern "C" void kernel_launch(void* const* d_in, const int* in_sizes, int n_in,
                              void* d_out, int out_size)
{
    const float* Wd = nullptr;
    const float* Wc = nullptr;
    for (int i = 0; i < n_in; i++) {
        if (in_sizes[i] == 3) Wd = (const float*)d_in[i];
        else if (in_sizes[i] == 9) Wc = (const float*)d_in[i];
    }
    int N = (out_size % 10 == 0) ? (out_size / 10) : (in_sizes[0] / 3);

    const float* ro = nullptr;
    const float* rd = nullptr;
    for (int i = 0; i < n_in; i++) {
        if (in_sizes[i] == 3 * N && in_sizes[i] > 9) {
            if (!ro) ro = (const float*)d_in[i];
            else if (!rd) { rd = (const float*)d_in[i]; break; }
        }
    }
    if (!ro || !rd) { ro = (const float*)d_in[0]; rd = (const float*)d_in[1]; }
    if (!Wd) Wd = (const float*)d_in[3];
    if (!Wc) Wc = (const float*)d_in[4];

    float* out = (float*)d_out;
    const int threads = 256;
    const int blocks  = (N + threads - 1) / threads;
    volume_render_kernel<<<blocks, threads>>>(ro, rd, Wd, Wc, out,
                                              N, (long long)out_size);
}

// round 6
// speedup vs baseline: 2.5868x; 1.6255x over previous
#include <cuda_runtime.h>
#include <stdint.h>

// VolumeRenderer: two-pass NeRF. One thread per ray.
// R6: convergent single-call-site fine loop (fixed 127 trips: 63 bin advances
// + 64 importance emissions), tanh.approx sigmoids, base-2 softplus/alpha
// (log2e factors cancel exactly), no clamps, one rcp per importance sample.

constexpr int NS = 64;
constexpr int NI = 64;
constexpr float NEARP = 2.0f;
constexpr float FARP  = 6.0f;
constexpr float EPS_W = 1e-5f;
constexpr float EPS_T = 1e-10f;
constexpr float FAR_DIST = 1e10f;
constexpr float LOG2E = 1.44269504088896340736f;

__device__ __forceinline__ float ex2a(float x){ float y; asm("ex2.approx.f32 %0,%1;":"=f"(y):"f"(x)); return y; }
__device__ __forceinline__ float lg2a(float x){ float y; asm("lg2.approx.f32 %0,%1;":"=f"(y):"f"(x)); return y; }
__device__ __forceinline__ float tanha(float x){ float y; asm("tanh.approx.f32 %0,%1;":"=f"(y):"f"(x)); return y; }
__device__ __forceinline__ float rcpa(float x){ float y; asm("rcp.approx.f32 %0,%1;":"=f"(y):"f"(x)); return y; }

// densL = softplus(x)*log2e, given xL = x*log2e. Tiny-e tail kept via poly
// (the R1 7e-2 bug). log2(1+e) = log1p(e)*log2e.
__device__ __forceinline__ float densL_from(float xL) {
    float e = ex2a(-fabsf(xL));
    float lsmall = (e * LOG2E) * fmaf(e, fmaf(e, 0.33333334f, -0.5f), 1.0f);
    float lbig   = lg2a(1.0f + e);
    float l = (e < 0.03f) ? lsmall : lbig;
    return fmaxf(xL, 0.0f) + l;
}

__global__ __launch_bounds__(128)
void volume_render_kernel(const float* __restrict__ ro_g,
                          const float* __restrict__ rd_g,
                          const float* __restrict__ Wd_g,
                          const float* __restrict__ Wc_g,
                          float* __restrict__ out,
                          int N, long long out_size)
{
    const int ray = blockIdx.x * blockDim.x + threadIdx.x;
    if (ray >= N) return;

    const long long NL = (long long)N;

    const float ro0 = ro_g[ray*3+0], ro1 = ro_g[ray*3+1], ro2 = ro_g[ray*3+2];
    const float rd0 = rd_g[ray*3+0], rd1 = rd_g[ray*3+1], rd2 = rd_g[ray*3+2];

    const float wd0 = __ldg(Wd_g+0), wd1 = __ldg(Wd_g+1), wd2 = __ldg(Wd_g+2);

    // density argument scaled by log2e: xL(t) = A0L + B0L*t
    const float A0L = (ro0*wd0 + ro1*wd1 + ro2*wd2) * LOG2E;
    const float B0L = (rd0*wd0 + rd1*wd1 + rd2*wd2) * LOG2E;

    // color: sigmoid(Ac+Bc*t) = 0.5*tanh(0.5*(Ac+Bc*t)) + 0.5 -> half-args
    float AcH0, AcH1, AcH2, BcH0, BcH1, BcH2;
    {
        float w00=__ldg(Wc_g+0), w01=__ldg(Wc_g+1), w02=__ldg(Wc_g+2);
        float w10=__ldg(Wc_g+3), w11=__ldg(Wc_g+4), w12=__ldg(Wc_g+5);
        float w20=__ldg(Wc_g+6), w21=__ldg(Wc_g+7), w22=__ldg(Wc_g+8);
        AcH0 = 0.5f*(ro0*w00 + ro1*w10 + ro2*w20);
        AcH1 = 0.5f*(ro0*w01 + ro1*w11 + ro2*w21);
        AcH2 = 0.5f*(ro0*w02 + ro1*w12 + ro2*w22);
        BcH0 = 0.5f*(rd0*w00 + rd1*w10 + rd2*w20);
        BcH1 = 0.5f*(rd0*w01 + rd1*w11 + rd2*w21);
        BcH2 = 0.5f*(rd0*w02 + rd1*w12 + rd2*w22);
    }

    const float STEP = (FARP - NEARP) / 63.0f;

    // ---------------- coarse pass ----------------
    float w[NS];
    float trans = 1.0f;
    float r0 = 0.f, r1 = 0.f, r2 = 0.f, depth = 0.f, acc = 0.f, wsum = 0.f;

    #pragma unroll 8
    for (int i = 0; i < NS; i++) {
        float t     = fmaf(STEP, (float)i, NEARP);
        float densL = densL_from(fmaf(B0L, t, A0L));
        float dist  = (i < NS-1) ? STEP : FAR_DIST;
        float ta    = ex2a(-densL * dist);       // = exp(-dens*dist)
        float wi    = (1.0f - ta) * trans;
        w[i] = wi;
        float wh = 0.5f * wi;
        r0 += fmaf(wh, tanha(fmaf(BcH0, t, AcH0)), wh);
        r1 += fmaf(wh, tanha(fmaf(BcH1, t, AcH1)), wh);
        r2 += fmaf(wh, tanha(fmaf(BcH2, t, AcH2)), wh);
        depth = fmaf(wi, t, depth);
        acc  += wi;
        wsum += wi + EPS_W;
        trans *= (ta + EPS_T);
    }

    if (3*NL <= out_size) {
        out[(long long)ray*3+0] = r0 + (1.0f - acc);
        out[(long long)ray*3+1] = r1 + (1.0f - acc);
        out[(long long)ray*3+2] = r2 + (1.0f - acc);
    }
    if (4*NL <= out_size) out[3*NL + ray] = depth;
    if (5*NL <= out_size) out[4*NL + ray] = acc;

    // ------- fused importance sampling + merge + fine render, CONVERGENT -------
    // Merged stream = t_0, then 127 emissions: exactly 63 bin-advances and 64
    // importance samples in data-dependent order. One render per iteration.
    float ftr = 1.0f;
    float fr0 = 0.f, fr1 = 0.f, fr2 = 0.f, fdep = 0.f, facc = 0.f;

    const float inv_wsum = rcpa(wsum);
    int   b = 0, k = 0;
    float cdfb  = 0.0f;
    float cdfb1 = (w[0] + EPS_W) * inv_wsum;
    float tb    = NEARP;
    float uk    = 0.0f;
    float pend  = NEARP;                  // first merged sample = t_0

    #pragma unroll 1
    for (int it = 1; it < NS + NI; it++) {
        // choose next merged sample (short divergent arms, render is shared)
        bool takeImp = (k < NI) && ((uk < cdfb1) || (b == NS-1));
        float s;
        if (takeImp) {
            float denom = cdfb1 - cdfb;
            if (denom < EPS_W) denom = 1.0f;
            float dt = (b < NS-1) ? STEP : 0.0f;   // t[clip(b+1)] - t[b]
            s = fmaf((uk - cdfb) * rcpa(denom), dt, tb);
            k++;
            uk = (k == NI-1) ? 1.0f : (float)k * (1.0f/63.0f);
        } else {
            b++;
            cdfb  = cdfb1;
            cdfb1 = cdfb + (w[b] + EPS_W) * inv_wsum;
            tb   += STEP;
            s = tb;
        }
        // convergent render of previous sample with dist = s - pend
        {
            float t     = pend;
            float densL = densL_from(fmaf(B0L, t, A0L));
            float ta    = ex2a(-densL * (s - t));
            float wi    = (1.0f - ta) * ftr;
            float wh    = 0.5f * wi;
            fr0 += fmaf(wh, tanha(fmaf(BcH0, t, AcH0)), wh);
            fr1 += fmaf(wh, tanha(fmaf(BcH1, t, AcH1)), wh);
            fr2 += fmaf(wh, tanha(fmaf(BcH2, t, AcH2)), wh);
            fdep = fmaf(wi, t, fdep);
            facc += wi;
            ftr  *= (ta + EPS_T);
        }
        pend = s;
    }
    // last merged sample rendered with FAR_DIST
    {
        float t     = pend;
        float densL = densL_from(fmaf(B0L, t, A0L));
        float ta    = ex2a(-densL * FAR_DIST);
        float wi    = (1.0f - ta) * ftr;
        float wh    = 0.5f * wi;
        fr0 += fmaf(wh, tanha(fmaf(BcH0, t, AcH0)), wh);
        fr1 += fmaf(wh, tanha(fmaf(BcH1, t, AcH1)), wh);
        fr2 += fmaf(wh, tanha(fmaf(BcH2, t, AcH2)), wh);
        fdep = fmaf(wi, t, fdep);
        facc += wi;
    }

    if (8*NL <= out_size) {
        out[5*NL + (long long)ray*3 + 0] = fr0 + (1.0f - facc);
        out[5*NL + (long long)ray*3 + 1] = fr1 + (1.0f - facc);
        out[5*NL + (long long)ray*3 + 2] = fr2 + (1.0f - facc);
    }
    if (9*NL  <= out_size) out[8*NL + ray] = fdep;
    if (10*NL <= out_size) out[9*NL + ray] = facc;
}

extern "C" void kernel_launch(void* const* d_in, const int* in_sizes, int n_in,
                              void* d_out, int out_size)
{
    const float* Wd = nullptr;
    const float* Wc = nullptr;
    for (int i = 0; i < n_in; i++) {
        if (in_sizes[i] == 3) Wd = (const float*)d_in[i];
        else if (in_sizes[i] == 9) Wc = (const float*)d_in[i];
    }
    int N = (out_size % 10 == 0) ? (out_size / 10) : (in_sizes[0] / 3);

    const float* ro = nullptr;
    const float* rd = nullptr;
    for (int i = 0; i < n_in; i++) {
        if (in_sizes[i] == 3 * N && in_sizes[i] > 9) {
            if (!ro) ro = (const float*)d_in[i];
            else if (!rd) { rd = (const float*)d_in[i]; break; }
        }
    }
    if (!ro || !rd) { ro = (const float*)d_in[0]; rd = (const float*)d_in[1]; }
    if (!Wd) Wd = (const float*)d_in[3];
    if (!Wc) Wc = (const float*)d_in[4];

    float* out = (float*)d_out;
    const int threads = 128;
    const int blocks  = (N + threads - 1) / threads;
    volume_render_kernel<<<blocks, threads>>>(ro, rd, Wd, Wc, out,
                                              N, (long long)out_size);
}

// round 7
// speedup vs baseline: 3.0100x; 1.1636x over previous
#include <cuda_runtime.h>
#include <stdint.h>

// VolumeRenderer: two-pass NeRF. One thread per ray.
// R7: branchless predicated fine sampler (no BSSY/BSYNC, no divergence) +
// software-pipelined render (density/color MUFUs for sample s issued in the
// iteration that produces s; alpha/accumulate consume them next iteration).

constexpr int NS = 64;
constexpr int NI = 64;
constexpr float NEARP = 2.0f;
constexpr float FARP  = 6.0f;
constexpr float EPS_W = 1e-5f;
constexpr float EPS_T = 1e-10f;
constexpr float FAR_DIST = 1e10f;
constexpr float LOG2E = 1.44269504088896340736f;

__device__ __forceinline__ float ex2a(float x){ float y; asm("ex2.approx.f32 %0,%1;":"=f"(y):"f"(x)); return y; }
__device__ __forceinline__ float lg2a(float x){ float y; asm("lg2.approx.f32 %0,%1;":"=f"(y):"f"(x)); return y; }
__device__ __forceinline__ float tanha(float x){ float y; asm("tanh.approx.f32 %0,%1;":"=f"(y):"f"(x)); return y; }
__device__ __forceinline__ float rcpa(float x){ float y; asm("rcp.approx.f32 %0,%1;":"=f"(y):"f"(x)); return y; }

// densL = softplus(x)*log2e, given xL = x*log2e. Tiny-e tail kept via poly
// (the R1 7e-2 bug). log2(1+e) = log1p(e)*log2e.
__device__ __forceinline__ float densL_from(float xL) {
    float e = ex2a(-fabsf(xL));
    float lsmall = (e * LOG2E) * fmaf(e, fmaf(e, 0.33333334f, -0.5f), 1.0f);
    float lbig   = lg2a(1.0f + e);
    float l = (e < 0.03f) ? lsmall : lbig;
    return fmaxf(xL, 0.0f) + l;
}

__global__ __launch_bounds__(128)
void volume_render_kernel(const float* __restrict__ ro_g,
                          const float* __restrict__ rd_g,
                          const float* __restrict__ Wd_g,
                          const float* __restrict__ Wc_g,
                          float* __restrict__ out,
                          int N, long long out_size)
{
    const int ray = blockIdx.x * blockDim.x + threadIdx.x;
    if (ray >= N) return;

    const long long NL = (long long)N;

    const float ro0 = ro_g[ray*3+0], ro1 = ro_g[ray*3+1], ro2 = ro_g[ray*3+2];
    const float rd0 = rd_g[ray*3+0], rd1 = rd_g[ray*3+1], rd2 = rd_g[ray*3+2];

    const float wd0 = __ldg(Wd_g+0), wd1 = __ldg(Wd_g+1), wd2 = __ldg(Wd_g+2);

    // density argument scaled by log2e: xL(t) = A0L + B0L*t
    const float A0L = (ro0*wd0 + ro1*wd1 + ro2*wd2) * LOG2E;
    const float B0L = (rd0*wd0 + rd1*wd1 + rd2*wd2) * LOG2E;

    // color: sigmoid(Ac+Bc*t) = 0.5*tanh(0.5*(Ac+Bc*t)) + 0.5 -> half-args
    float AcH0, AcH1, AcH2, BcH0, BcH1, BcH2;
    {
        float w00=__ldg(Wc_g+0), w01=__ldg(Wc_g+1), w02=__ldg(Wc_g+2);
        float w10=__ldg(Wc_g+3), w11=__ldg(Wc_g+4), w12=__ldg(Wc_g+5);
        float w20=__ldg(Wc_g+6), w21=__ldg(Wc_g+7), w22=__ldg(Wc_g+8);
        AcH0 = 0.5f*(ro0*w00 + ro1*w10 + ro2*w20);
        AcH1 = 0.5f*(ro0*w01 + ro1*w11 + ro2*w21);
        AcH2 = 0.5f*(ro0*w02 + ro1*w12 + ro2*w22);
        BcH0 = 0.5f*(rd0*w00 + rd1*w10 + rd2*w20);
        BcH1 = 0.5f*(rd0*w01 + rd1*w11 + rd2*w21);
        BcH2 = 0.5f*(rd0*w02 + rd1*w12 + rd2*w22);
    }

    const float STEP = (FARP - NEARP) / 63.0f;

    // ---------------- coarse pass ----------------
    float w[NS];
    float trans = 1.0f;
    float r0 = 0.f, r1 = 0.f, r2 = 0.f, depth = 0.f, acc = 0.f, wsum = 0.f;

    #pragma unroll 8
    for (int i = 0; i < NS; i++) {
        float t     = fmaf(STEP, (float)i, NEARP);
        float densL = densL_from(fmaf(B0L, t, A0L));
        float dist  = (i < NS-1) ? STEP : FAR_DIST;
        float ta    = ex2a(-densL * dist);       // = exp(-dens*dist)
        float wi    = (1.0f - ta) * trans;
        w[i] = wi;
        float wh = 0.5f * wi;
        r0 += fmaf(wh, tanha(fmaf(BcH0, t, AcH0)), wh);
        r1 += fmaf(wh, tanha(fmaf(BcH1, t, AcH1)), wh);
        r2 += fmaf(wh, tanha(fmaf(BcH2, t, AcH2)), wh);
        depth = fmaf(wi, t, depth);
        acc  += wi;
        wsum += wi + EPS_W;
        trans *= (ta + EPS_T);
    }

    if (3*NL <= out_size) {
        out[(long long)ray*3+0] = r0 + (1.0f - acc);
        out[(long long)ray*3+1] = r1 + (1.0f - acc);
        out[(long long)ray*3+2] = r2 + (1.0f - acc);
    }
    if (4*NL <= out_size) out[3*NL + ray] = depth;
    if (5*NL <= out_size) out[4*NL + ray] = acc;

    // ------- fused sampler + merge + fine render: branchless + pipelined -------
    // Merged stream = t_0, then 127 emissions: exactly 63 bin-advances + 64
    // importance samples. Each iteration: (a) branchless next-sample selection,
    // (b) render PREVIOUS sample using MUFU results issued last iteration,
    // (c) issue density/color MUFUs for the new sample.
    float ftr = 1.0f;
    float fr0 = 0.f, fr1 = 0.f, fr2 = 0.f, fdep = 0.f, facc = 0.f;

    const float inv_wsum = rcpa(wsum);
    int   b = 0, k = 0;
    float cdfb  = 0.0f;
    float cdfb1 = (w[0] + EPS_W) * inv_wsum;
    float tb    = NEARP;
    float uk    = 0.0f;

    float pend = NEARP;                                   // first merged sample
    float pdL  = densL_from(fmaf(B0L, NEARP, A0L));       // pipelined density
    float pc0  = tanha(fmaf(BcH0, NEARP, AcH0));          // pipelined colors
    float pc1  = tanha(fmaf(BcH1, NEARP, AcH1));
    float pc2  = tanha(fmaf(BcH2, NEARP, AcH2));

    #pragma unroll 1
    for (int it = 1; it < NS + NI; it++) {
        // ---- branchless selection of next merged sample s ----
        bool  imp   = (k < NI) && ((uk < cdfb1) || (b == NS-1));
        float denom = cdfb1 - cdfb;
        denom = (denom < EPS_W) ? 1.0f : denom;
        float dt    = (b < NS-1) ? STEP : 0.0f;
        float s_imp = fmaf((uk - cdfb) * rcpa(denom), dt, tb);
        float s_adv = tb + STEP;
        float s     = imp ? s_imp : s_adv;
        // predicated state updates (arms touch disjoint state)
        int   bn    = imp ? b : (b + 1);
        float wb    = w[bn];                                // bn <= 63 always
        float ncdf1 = cdfb1 + (wb + EPS_W) * inv_wsum;
        cdfb  = imp ? cdfb  : cdfb1;
        cdfb1 = imp ? cdfb1 : ncdf1;
        tb    = imp ? tb    : s_adv;
        b     = bn;
        k    += imp ? 1 : 0;
        float un = (k == NI-1) ? 1.0f : (float)k * (1.0f/63.0f);
        uk    = imp ? un : uk;

        // ---- render previous sample (uses pipelined pdL / pc*) ----
        float ta = ex2a(-pdL * (s - pend));
        float wi = (1.0f - ta) * ftr;
        float wh = 0.5f * wi;
        fr0 += fmaf(wh, pc0, wh);
        fr1 += fmaf(wh, pc1, wh);
        fr2 += fmaf(wh, pc2, wh);
        fdep = fmaf(wi, pend, fdep);
        facc += wi;
        ftr  *= (ta + EPS_T);

        // ---- issue MUFUs for the new sample ----
        pend = s;
        pdL  = densL_from(fmaf(B0L, s, A0L));
        pc0  = tanha(fmaf(BcH0, s, AcH0));
        pc1  = tanha(fmaf(BcH1, s, AcH1));
        pc2  = tanha(fmaf(BcH2, s, AcH2));
    }
    // last merged sample rendered with FAR_DIST
    {
        float ta = ex2a(-pdL * FAR_DIST);
        float wi = (1.0f - ta) * ftr;
        float wh = 0.5f * wi;
        fr0 += fmaf(wh, pc0, wh);
        fr1 += fmaf(wh, pc1, wh);
        fr2 += fmaf(wh, pc2, wh);
        fdep = fmaf(wi, pend, fdep);
        facc += wi;
    }

    if (8*NL <= out_size) {
        out[5*NL + (long long)ray*3 + 0] = fr0 + (1.0f - facc);
        out[5*NL + (long long)ray*3 + 1] = fr1 + (1.0f - facc);
        out[5*NL + (long long)ray*3 + 2] = fr2 + (1.0f - facc);
    }
    if (9*NL  <= out_size) out[8*NL + ray] = fdep;
    if (10*NL <= out_size) out[9*NL + ray] = facc;
}

extern "C" void kernel_launch(void* const* d_in, const int* in_sizes, int n_in,
                              void* d_out, int out_size)
{
    const float* Wd = nullptr;
    const float* Wc = nullptr;
    for (int i = 0; i < n_in; i++) {
        if (in_sizes[i] == 3) Wd = (const float*)d_in[i];
        else if (in_sizes[i] == 9) Wc = (const float*)d_in[i];
    }
    int N = (out_size % 10 == 0) ? (out_size / 10) : (in_sizes[0] / 3);

    const float* ro = nullptr;
    const float* rd = nullptr;
    for (int i = 0; i < n_in; i++) {
        if (in_sizes[i] == 3 * N && in_sizes[i] > 9) {
            if (!ro) ro = (const float*)d_in[i];
            else if (!rd) { rd = (const float*)d_in[i]; break; }
        }
    }
    if (!ro || !rd) { ro = (const float*)d_in[0]; rd = (const float*)d_in[1]; }
    if (!Wd) Wd = (const float*)d_in[3];
    if (!Wc) Wc = (const float*)d_in[4];

    float* out = (float*)d_out;
    const int threads = 128;
    const int blocks  = (N + threads - 1) / threads;
    volume_render_kernel<<<blocks, threads>>>(ro, rd, Wd, Wc, out,
                                              N, (long long)out_size);
}

// round 9
// speedup vs baseline: 3.0267x; 1.0055x over previous
#include <cuda_runtime.h>
#include <stdint.h>

// VolumeRenderer: two-pass NeRF. One thread per ray.
// R8: cheap 2-MUFU softplus for all interior samples (tail-preserving version
// only where dist=FAR_DIST: coarse i=63 and the final fine sample, which is
// always t=FARP); fully unrolled coarse pass (constant t/dist, static w[]);
// w+EPS_W stored once.

constexpr int NS = 64;
constexpr int NI = 64;
constexpr float NEARP = 2.0f;
constexpr float FARP  = 6.0f;
constexpr float EPS_W = 1e-5f;
constexpr float EPS_T = 1e-10f;
constexpr float FAR_DIST = 1e10f;
constexpr float LOG2E = 1.44269504088896340736f;

__device__ __forceinline__ float ex2a(float x){ float y; asm("ex2.approx.f32 %0,%1;":"=f"(y):"f"(x)); return y; }
__device__ __forceinline__ float lg2a(float x){ float y; asm("lg2.approx.f32 %0,%1;":"=f"(y):"f"(x)); return y; }
__device__ __forceinline__ float tanha(float x){ float y; asm("tanh.approx.f32 %0,%1;":"=f"(y):"f"(x)); return y; }
__device__ __forceinline__ float rcpa(float x){ float y; asm("rcp.approx.f32 %0,%1;":"=f"(y):"f"(x)); return y; }

// Cheap softplus*log2e given xL = x*log2e. Loses the tiny-density tail
// (2^xL for xL << -20 rounds away in 1+e) — fine wherever dist <= ~4.
// |xL| stays far below 127 for this data, so no overflow.
__device__ __forceinline__ float densL_cheap(float xL) {
    return lg2a(1.0f + ex2a(xL));
}

// Tail-preserving softplus*log2e (poly for tiny e) — ONLY for FAR_DIST
// samples, where dens ~ 2^-30 still matters (the R1 7e-2 bug).
__device__ __forceinline__ float densL_exact(float xL) {
    float e = ex2a(-fabsf(xL));
    float lsmall = (e * LOG2E) * fmaf(e, fmaf(e, 0.33333334f, -0.5f), 1.0f);
    float lbig   = lg2a(1.0f + e);
    float l = (e < 0.03f) ? lsmall : lbig;
    return fmaxf(xL, 0.0f) + l;
}

__global__ __launch_bounds__(128)
void volume_render_kernel(const float* __restrict__ ro_g,
                          const float* __restrict__ rd_g,
                          const float* __restrict__ Wd_g,
                          const float* __restrict__ Wc_g,
                          float* __restrict__ out,
                          int N, long long out_size)
{
    const int ray = blockIdx.x * blockDim.x + threadIdx.x;
    if (ray >= N) return;

    const long long NL = (long long)N;

    const float ro0 = ro_g[ray*3+0], ro1 = ro_g[ray*3+1], ro2 = ro_g[ray*3+2];
    const float rd0 = rd_g[ray*3+0], rd1 = rd_g[ray*3+1], rd2 = rd_g[ray*3+2];

    const float wd0 = __ldg(Wd_g+0), wd1 = __ldg(Wd_g+1), wd2 = __ldg(Wd_g+2);

    const float A0L = (ro0*wd0 + ro1*wd1 + ro2*wd2) * LOG2E;
    const float B0L = (rd0*wd0 + rd1*wd1 + rd2*wd2) * LOG2E;

    float AcH0, AcH1, AcH2, BcH0, BcH1, BcH2;
    {
        float w00=__ldg(Wc_g+0), w01=__ldg(Wc_g+1), w02=__ldg(Wc_g+2);
        float w10=__ldg(Wc_g+3), w11=__ldg(Wc_g+4), w12=__ldg(Wc_g+5);
        float w20=__ldg(Wc_g+6), w21=__ldg(Wc_g+7), w22=__ldg(Wc_g+8);
        AcH0 = 0.5f*(ro0*w00 + ro1*w10 + ro2*w20);
        AcH1 = 0.5f*(ro0*w01 + ro1*w11 + ro2*w21);
        AcH2 = 0.5f*(ro0*w02 + ro1*w12 + ro2*w22);
        BcH0 = 0.5f*(rd0*w00 + rd1*w10 + rd2*w20);
        BcH1 = 0.5f*(rd0*w01 + rd1*w11 + rd2*w21);
        BcH2 = 0.5f*(rd0*w02 + rd1*w12 + rd2*w22);
    }

    const float STEP = (FARP - NEARP) / 63.0f;

    // ---------------- coarse pass (fully unrolled; i=63 uses exact tail) ------
    float wpe[NS];                       // w_i + EPS_W
    float trans = 1.0f;
    float r0 = 0.f, r1 = 0.f, r2 = 0.f, depth = 0.f, acc = 0.f, wsum = 0.f;

    #pragma unroll
    for (int i = 0; i < NS; i++) {
        const float t = NEARP + STEP * (float)i;      // compile-time constant
        float xL = fmaf(B0L, t, A0L);
        float ta;
        if (i < NS-1) {
            ta = ex2a(-densL_cheap(xL) * STEP);       // exp(-dens*STEP)
        } else {
            ta = ex2a(-densL_exact(xL) * FAR_DIST);   // tail matters here
        }
        float wi = (1.0f - ta) * trans;
        wpe[i] = wi + EPS_W;
        float wh = 0.5f * wi;
        r0 += fmaf(wh, tanha(fmaf(BcH0, t, AcH0)), wh);
        r1 += fmaf(wh, tanha(fmaf(BcH1, t, AcH1)), wh);
        r2 += fmaf(wh, tanha(fmaf(BcH2, t, AcH2)), wh);
        depth = fmaf(wi, t, depth);
        acc  += wi;
        wsum += wi + EPS_W;
        trans *= (ta + EPS_T);
    }

    if (3*NL <= out_size) {
        out[(long long)ray*3+0] = r0 + (1.0f - acc);
        out[(long long)ray*3+1] = r1 + (1.0f - acc);
        out[(long long)ray*3+2] = r2 + (1.0f - acc);
    }
    if (4*NL <= out_size) out[3*NL + ray] = depth;
    if (5*NL <= out_size) out[4*NL + ray] = acc;

    // ------- fused sampler + merge + fine render: branchless + pipelined -------
    float ftr = 1.0f;
    float fr0 = 0.f, fr1 = 0.f, fr2 = 0.f, fdep = 0.f, facc = 0.f;

    const float inv_wsum = rcpa(wsum);
    int   b = 0, k = 0;
    float cdfb  = 0.0f;
    float cdfb1 = wpe[0] * inv_wsum;
    float tb    = NEARP;
    float uk    = 0.0f;

    float pend = NEARP;                                   // first merged sample
    float pdL  = densL_cheap(fmaf(B0L, NEARP, A0L));      // pipelined density
    float pc0  = tanha(fmaf(BcH0, NEARP, AcH0));          // pipelined colors
    float pc1  = tanha(fmaf(BcH1, NEARP, AcH1));
    float pc2  = tanha(fmaf(BcH2, NEARP, AcH2));

    #pragma unroll 1
    for (int it = 1; it < NS + NI; it++) {
        // ---- branchless selection of next merged sample s ----
        bool  imp   = (k < NI) && ((uk < cdfb1) || (b == NS-1));
        float denom = cdfb1 - cdfb;
        denom = (denom < EPS_W) ? 1.0f : denom;
        float dt    = (b < NS-1) ? STEP : 0.0f;
        float s_imp = fmaf((uk - cdfb) * rcpa(denom), dt, tb);
        float s_adv = tb + STEP;
        float s     = imp ? s_imp : s_adv;
        int   bn    = imp ? b : (b + 1);
        float ncdf1 = cdfb1 + wpe[bn] * inv_wsum;         // bn <= 63 always
        cdfb  = imp ? cdfb  : cdfb1;
        cdfb1 = imp ? cdfb1 : ncdf1;
        tb    = imp ? tb    : s_adv;
        b     = bn;
        k    += imp ? 1 : 0;
        float un = (k == NI-1) ? 1.0f : (float)k * (1.0f/63.0f);
        uk    = imp ? un : uk;

        // ---- render previous sample (uses pipelined pdL / pc*) ----
        float ta = ex2a(-pdL * (s - pend));
        float wi = (1.0f - ta) * ftr;
        float wh = 0.5f * wi;
        fr0 += fmaf(wh, pc0, wh);
        fr1 += fmaf(wh, pc1, wh);
        fr2 += fmaf(wh, pc2, wh);
        fdep = fmaf(wi, pend, fdep);
        facc += wi;
        ftr  *= (ta + EPS_T);

        // ---- issue MUFUs for the new sample (cheap: dist <= STEP next) ----
        pend = s;
        pdL  = densL_cheap(fmaf(B0L, s, A0L));
        pc0  = tanha(fmaf(BcH0, s, AcH0));
        pc1  = tanha(fmaf(BcH1, s, AcH1));
        pc2  = tanha(fmaf(BcH2, s, AcH2));
    }
    // Last merged sample is ALWAYS t = FARP (importance samples never exceed
    // t63). Rendered with FAR_DIST -> needs the tail-preserving density.
    {
        float xL = fmaf(B0L, FARP, A0L);
        float ta = ex2a(-densL_exact(xL) * FAR_DIST);
        float wi = (1.0f - ta) * ftr;
        float wh = 0.5f * wi;
        fr0 += fmaf(wh, tanha(fmaf(BcH0, FARP, AcH0)), wh);
        fr1 += fmaf(wh, tanha(fmaf(BcH1, FARP, AcH1)), wh);
        fr2 += fmaf(wh, tanha(fmaf(BcH2, FARP, AcH2)), wh);
        fdep = fmaf(wi, FARP, fdep);
        facc += wi;
    }

    if (8*NL <= out_size) {
        out[5*NL + (long long)ray*3 + 0] = fr0 + (1.0f - facc);
        out[5*NL + (long long)ray*3 + 1] = fr1 + (1.0f - facc);
        out[5*NL + (long long)ray*3 + 2] = fr2 + (1.0f - facc);
    }
    if (9*NL  <= out_size) out[8*NL + ray] = fdep;
    if (10*NL <= out_size) out[9*NL + ray] = facc;
}

extern "C" void kernel_launch(void* const* d_in, const int* in_sizes, int n_in,
                              void* d_out, int out_size)
{
    const float* Wd = nullptr;
    const float* Wc = nullptr;
    for (int i = 0; i < n_in; i++) {
        if (in_sizes[i] == 3) Wd = (const float*)d_in[i];
        else if (in_sizes[i] == 9) Wc = (const float*)d_in[i];
    }
    int N = (out_size % 10 == 0) ? (out_size / 10) : (in_sizes[0] / 3);

    const float* ro = nullptr;
    const float* rd = nullptr;
    for (int i = 0; i < n_in; i++) {
        if (in_sizes[i] == 3 * N && in_sizes[i] > 9) {
            if (!ro) ro = (const float*)d_in[i];
            else if (!rd) { rd = (const float*)d_in[i]; break; }
        }
    }
    if (!ro || !rd) { ro = (const float*)d_in[0]; rd = (const float*)d_in[1]; }
    if (!Wd) Wd = (const float*)d_in[3];
    if (!Wc) Wc = (const float*)d_in[4];

    float* out = (float*)d_out;
    const int threads = 128;
    const int blocks  = (N + threads - 1) / threads;
    volume_render_kernel<<<blocks, threads>>>(ro, rd, Wd, Wc, out,
                                              N, (long long)out_size);
}

// round 11
// speedup vs baseline: 3.3521x; 1.1075x over previous
#include <cuda_runtime.h>
#include <stdint.h>

// VolumeRenderer: two-pass NeRF. One thread per ray.
// R10: log-space transmittance (EPS_T dropped -> carried chain is ONE FMA,
// ex2 off the critical path), unnormalized prefix-CDF sampler (1/wsum cancels),
// prefetched pre[] rotation, unroll-2 fine loop.

constexpr int NS = 64;
constexpr int NI = 64;
constexpr float NEARP = 2.0f;
constexpr float FARP  = 6.0f;
constexpr float EPS_W = 1e-5f;
constexpr float FAR_DIST = 1e10f;
constexpr float LOG2E = 1.44269504088896340736f;

__device__ __forceinline__ float ex2a(float x){ float y; asm("ex2.approx.f32 %0,%1;":"=f"(y):"f"(x)); return y; }
__device__ __forceinline__ float lg2a(float x){ float y; asm("lg2.approx.f32 %0,%1;":"=f"(y):"f"(x)); return y; }
__device__ __forceinline__ float tanha(float x){ float y; asm("tanh.approx.f32 %0,%1;":"=f"(y):"f"(x)); return y; }
__device__ __forceinline__ float rcpa(float x){ float y; asm("rcp.approx.f32 %0,%1;":"=f"(y):"f"(x)); return y; }

// Cheap softplus*log2e (interior samples, dist <= ~4).
__device__ __forceinline__ float densL_cheap(float xL) {
    return lg2a(1.0f + ex2a(xL));
}
// Tail-preserving softplus*log2e — only where dist = FAR_DIST (R1 bug).
__device__ __forceinline__ float densL_exact(float xL) {
    float e = ex2a(-fabsf(xL));
    float lsmall = (e * LOG2E) * fmaf(e, fmaf(e, 0.33333334f, -0.5f), 1.0f);
    float lbig   = lg2a(1.0f + e);
    float l = (e < 0.03f) ? lsmall : lbig;
    return fmaxf(xL, 0.0f) + l;
}

__global__ __launch_bounds__(128)
void volume_render_kernel(const float* __restrict__ ro_g,
                          const float* __restrict__ rd_g,
                          const float* __restrict__ Wd_g,
                          const float* __restrict__ Wc_g,
                          float* __restrict__ out,
                          int N, long long out_size)
{
    const int ray = blockIdx.x * blockDim.x + threadIdx.x;
    if (ray >= N) return;

    const long long NL = (long long)N;

    const float ro0 = ro_g[ray*3+0], ro1 = ro_g[ray*3+1], ro2 = ro_g[ray*3+2];
    const float rd0 = rd_g[ray*3+0], rd1 = rd_g[ray*3+1], rd2 = rd_g[ray*3+2];

    const float wd0 = __ldg(Wd_g+0), wd1 = __ldg(Wd_g+1), wd2 = __ldg(Wd_g+2);

    const float A0L = (ro0*wd0 + ro1*wd1 + ro2*wd2) * LOG2E;
    const float B0L = (rd0*wd0 + rd1*wd1 + rd2*wd2) * LOG2E;

    float AcH0, AcH1, AcH2, BcH0, BcH1, BcH2;
    {
        float w00=__ldg(Wc_g+0), w01=__ldg(Wc_g+1), w02=__ldg(Wc_g+2);
        float w10=__ldg(Wc_g+3), w11=__ldg(Wc_g+4), w12=__ldg(Wc_g+5);
        float w20=__ldg(Wc_g+6), w21=__ldg(Wc_g+7), w22=__ldg(Wc_g+8);
        AcH0 = 0.5f*(ro0*w00 + ro1*w10 + ro2*w20);
        AcH1 = 0.5f*(ro0*w01 + ro1*w11 + ro2*w21);
        AcH2 = 0.5f*(ro0*w02 + ro1*w12 + ro2*w22);
        BcH0 = 0.5f*(rd0*w00 + rd1*w10 + rd2*w20);
        BcH1 = 0.5f*(rd0*w01 + rd1*w11 + rd2*w21);
        BcH2 = 0.5f*(rd0*w02 + rd1*w12 + rd2*w22);
    }

    const float STEP = (FARP - NEARP) / 63.0f;

    // -------- coarse pass: log-space transmittance, unnormalized prefix CDF ----
    float pre[NS+1];                       // prefix sums of (w_i + EPS_W)
    pre[0] = 0.0f;
    float prew = 0.0f;
    float sumL = 0.0f;                     // optical depth in log2 space
    float Tp   = 1.0f;                     // transmittance before sample i
    float r0 = 0.f, r1 = 0.f, r2 = 0.f, depth = 0.f, acc = 0.f;

    #pragma unroll
    for (int i = 0; i < NS; i++) {
        const float t = NEARP + STEP * (float)i;          // constant-folded
        float xL = fmaf(B0L, t, A0L);
        float inc = (i < NS-1) ? densL_cheap(xL) * STEP
                               : densL_exact(xL) * FAR_DIST;
        sumL += inc;                                      // carried: 1 FMA/add
        float Tn = ex2a(-sumL);                           // off carried path
        float wi = Tp - Tn;
        prew += wi + EPS_W;
        pre[i+1] = prew;
        float wh = 0.5f * wi;
        r0 += fmaf(wh, tanha(fmaf(BcH0, t, AcH0)), wh);
        r1 += fmaf(wh, tanha(fmaf(BcH1, t, AcH1)), wh);
        r2 += fmaf(wh, tanha(fmaf(BcH2, t, AcH2)), wh);
        depth = fmaf(wi, t, depth);
        acc  += wi;
        Tp = Tn;
    }
    const float wsum = prew;

    if (3*NL <= out_size) {
        out[(long long)ray*3+0] = r0 + (1.0f - acc);
        out[(long long)ray*3+1] = r1 + (1.0f - acc);
        out[(long long)ray*3+2] = r2 + (1.0f - acc);
    }
    if (4*NL <= out_size) out[3*NL + ray] = depth;
    if (5*NL <= out_size) out[4*NL + ray] = acc;

    // -------- fused sampler + merge + fine render --------
    float fr0 = 0.f, fr1 = 0.f, fr2 = 0.f, fdep = 0.f, facc = 0.f;

    const float inv_wsum = rcpa(wsum);
    const float epsw_s   = EPS_W * wsum;   // degenerate-denominator threshold

    int   b = 0, k = 0;
    float tb    = NEARP;
    float preb  = 0.0f;                    // pre[b]
    float preb1 = pre[1];                  // pre[b+1]
    float preb2 = pre[2];                  // pre[b+2] (prefetched)
    float uk  = 0.0f;                      // current u
    float ukw = 0.0f;                      // u * wsum

    float pend = NEARP;                                   // pending sample
    float pdL  = densL_cheap(fmaf(B0L, NEARP, A0L));      // pipelined density
    float pc0  = tanha(fmaf(BcH0, NEARP, AcH0));          // pipelined colors
    float pc1  = tanha(fmaf(BcH1, NEARP, AcH1));
    float pc2  = tanha(fmaf(BcH2, NEARP, AcH2));

    float fsum = 0.0f;                     // fine-pass optical depth (log2)
    float fTp  = 1.0f;                     // transmittance before pending

    #pragma unroll 2
    for (int it = 1; it < NS + NI; it++) {
        // prefetch pre[b+2] for a potential advance this iteration
        int   bp = (b + 2 <= NS) ? (b + 2) : NS;
        float preload = pre[bp];

        // ---- branchless next-sample selection (unnormalized CDF) ----
        bool  imp  = (k < NI) && ((ukw < preb1) || (b == NS-1));
        float diff = preb1 - preb;
        bool  deg  = diff < epsw_s;
        float frnd = (ukw - preb) * rcpa(diff);
        float frd  = fmaf(-preb, inv_wsum, uk);           // (u - cdf0)/1
        float frac = deg ? frd : frnd;
        float dt   = (b < NS-1) ? STEP : 0.0f;
        float s_adv = tb + STEP;
        float s     = imp ? fmaf(frac, dt, tb) : s_adv;

        b     = imp ? b     : (b + 1);
        tb    = imp ? tb    : s_adv;
        preb  = imp ? preb  : preb1;
        preb1 = imp ? preb1 : preb2;
        preb2 = imp ? preb2 : preload;
        k    += imp ? 1 : 0;
        float un = (k == NI-1) ? 1.0f : (float)k * (1.0f/63.0f);
        uk    = imp ? un : uk;
        ukw   = imp ? un * wsum : ukw;

        // ---- render pending sample: carried chain is ONE fma (fsum) ----
        fsum = fmaf(pdL, s - pend, fsum);
        float Tn = ex2a(-fsum);                           // off carried path
        float wi = fTp - Tn;
        float wh = 0.5f * wi;
        fr0 += fmaf(wh, pc0, wh);
        fr1 += fmaf(wh, pc1, wh);
        fr2 += fmaf(wh, pc2, wh);
        fdep = fmaf(wi, pend, fdep);
        facc += wi;
        fTp = Tn;

        // ---- pipeline MUFUs for the new sample ----
        pend = s;
        pdL  = densL_cheap(fmaf(B0L, s, A0L));
        pc0  = tanha(fmaf(BcH0, s, AcH0));
        pc1  = tanha(fmaf(BcH1, s, AcH1));
        pc2  = tanha(fmaf(BcH2, s, AcH2));
    }
    // Last merged sample is ALWAYS t = FARP; dist = FAR_DIST needs exact tail.
    {
        float dL = densL_exact(fmaf(B0L, FARP, A0L));
        fsum = fmaf(dL, FAR_DIST, fsum);
        float Tn = ex2a(-fsum);                           // 0 unless tail tiny
        float wi = fTp - Tn;
        float wh = 0.5f * wi;
        fr0 += fmaf(wh, pc0, wh);                         // pc* already at FARP
        fr1 += fmaf(wh, pc1, wh);
        fr2 += fmaf(wh, pc2, wh);
        fdep = fmaf(wi, FARP, fdep);
        facc += wi;
    }

    if (8*NL <= out_size) {
        out[5*NL + (long long)ray*3 + 0] = fr0 + (1.0f - facc);
        out[5*NL + (long long)ray*3 + 1] = fr1 + (1.0f - facc);
        out[5*NL + (long long)ray*3 + 2] = fr2 + (1.0f - facc);
    }
    if (9*NL  <= out_size) out[8*NL + ray] = fdep;
    if (10*NL <= out_size) out[9*NL + ray] = facc;
}

extern "C" void kernel_launch(void* const* d_in, const int* in_sizes, int n_in,
                              void* d_out, int out_size)
{
    const float* Wd = nullptr;
    const float* Wc = nullptr;
    for (int i = 0; i < n_in; i++) {
        if (in_sizes[i] == 3) Wd = (const float*)d_in[i];
        else if (in_sizes[i] == 9) Wc = (const float*)d_in[i];
    }
    int N = (out_size % 10 == 0) ? (out_size / 10) : (in_sizes[0] / 3);

    const float* ro = nullptr;
    const float* rd = nullptr;
    for (int i = 0; i < n_in; i++) {
        if (in_sizes[i] == 3 * N && in_sizes[i] > 9) {
            if (!ro) ro = (const float*)d_in[i];
            else if (!rd) { rd = (const float*)d_in[i]; break; }
        }
    }
    if (!ro || !rd) { ro = (const float*)d_in[0]; rd = (const float*)d_in[1]; }
    if (!Wd) Wd = (const float*)d_in[3];
    if (!Wc) Wc = (const float*)d_in[4];

    float* out = (float*)d_out;
    const int threads = 128;
    const int blocks  = (N + threads - 1) / threads;
    volume_render_kernel<<<blocks, threads>>>(ro, rd, Wd, Wc, out,
                                              N, (long long)out_size);
}

// round 12
// speedup vs baseline: 3.4071x; 1.0164x over previous
#include <cuda_runtime.h>
#include <stdint.h>

// VolumeRenderer: two-pass NeRF. One thread per ray.
// R12: FIX preb2 prefetch off-by-one (pre[b+3], was pre[b+2] -> stale dup on
// consecutive bin advances, caused R10's 2.9e-4). Coarse density ex2 replaced
// by geometric recurrence (g *= r). Log-space transmittance + unnormalized
// prefix-CDF sampler retained.

constexpr int NS = 64;
constexpr int NI = 64;
constexpr float NEARP = 2.0f;
constexpr float FARP  = 6.0f;
constexpr float EPS_W = 1e-5f;
constexpr float FAR_DIST = 1e10f;
constexpr float LOG2E = 1.44269504088896340736f;

__device__ __forceinline__ float ex2a(float x){ float y; asm("ex2.approx.f32 %0,%1;":"=f"(y):"f"(x)); return y; }
__device__ __forceinline__ float lg2a(float x){ float y; asm("lg2.approx.f32 %0,%1;":"=f"(y):"f"(x)); return y; }
__device__ __forceinline__ float tanha(float x){ float y; asm("tanh.approx.f32 %0,%1;":"=f"(y):"f"(x)); return y; }
__device__ __forceinline__ float rcpa(float x){ float y; asm("rcp.approx.f32 %0,%1;":"=f"(y):"f"(x)); return y; }

// Cheap softplus*log2e (interior samples, dist <= ~4).
__device__ __forceinline__ float densL_cheap(float xL) {
    return lg2a(1.0f + ex2a(xL));
}
// Tail-preserving softplus*log2e — only where dist = FAR_DIST (R1 bug).
__device__ __forceinline__ float densL_exact(float xL) {
    float e = ex2a(-fabsf(xL));
    float lsmall = (e * LOG2E) * fmaf(e, fmaf(e, 0.33333334f, -0.5f), 1.0f);
    float lbig   = lg2a(1.0f + e);
    float l = (e < 0.03f) ? lsmall : lbig;
    return fmaxf(xL, 0.0f) + l;
}

__global__ __launch_bounds__(128)
void volume_render_kernel(const float* __restrict__ ro_g,
                          const float* __restrict__ rd_g,
                          const float* __restrict__ Wd_g,
                          const float* __restrict__ Wc_g,
                          float* __restrict__ out,
                          int N, long long out_size)
{
    const int ray = blockIdx.x * blockDim.x + threadIdx.x;
    if (ray >= N) return;

    const long long NL = (long long)N;

    const float ro0 = ro_g[ray*3+0], ro1 = ro_g[ray*3+1], ro2 = ro_g[ray*3+2];
    const float rd0 = rd_g[ray*3+0], rd1 = rd_g[ray*3+1], rd2 = rd_g[ray*3+2];

    const float wd0 = __ldg(Wd_g+0), wd1 = __ldg(Wd_g+1), wd2 = __ldg(Wd_g+2);

    const float A0L = (ro0*wd0 + ro1*wd1 + ro2*wd2) * LOG2E;
    const float B0L = (rd0*wd0 + rd1*wd1 + rd2*wd2) * LOG2E;

    float AcH0, AcH1, AcH2, BcH0, BcH1, BcH2;
    {
        float w00=__ldg(Wc_g+0), w01=__ldg(Wc_g+1), w02=__ldg(Wc_g+2);
        float w10=__ldg(Wc_g+3), w11=__ldg(Wc_g+4), w12=__ldg(Wc_g+5);
        float w20=__ldg(Wc_g+6), w21=__ldg(Wc_g+7), w22=__ldg(Wc_g+8);
        AcH0 = 0.5f*(ro0*w00 + ro1*w10 + ro2*w20);
        AcH1 = 0.5f*(ro0*w01 + ro1*w11 + ro2*w21);
        AcH2 = 0.5f*(ro0*w02 + ro1*w12 + ro2*w22);
        BcH0 = 0.5f*(rd0*w00 + rd1*w10 + rd2*w20);
        BcH1 = 0.5f*(rd0*w01 + rd1*w11 + rd2*w21);
        BcH2 = 0.5f*(rd0*w02 + rd1*w12 + rd2*w22);
    }

    const float STEP = (FARP - NEARP) / 63.0f;

    // -------- coarse pass: geometric density, log-space transmittance --------
    float pre[NS+1];                       // prefix sums of (w_i + EPS_W)
    pre[0] = 0.0f;
    float prew = 0.0f;
    float sumL = 0.0f;                     // optical depth (log2 space)
    float Tp   = 1.0f;
    float r0 = 0.f, r1 = 0.f, r2 = 0.f, depth = 0.f, acc = 0.f;

    // g_i = 2^(xL_i) on the uniform grid: geometric, one mul per step.
    float g = ex2a(fmaf(B0L, NEARP, A0L));
    const float gr = ex2a(B0L * STEP);

    #pragma unroll
    for (int i = 0; i < NS; i++) {
        const float t = NEARP + STEP * (float)i;          // constant-folded
        float inc;
        if (i < NS-1) {
            inc = lg2a(1.0f + g) * STEP;                  // densL_cheap via g
        } else {
            inc = densL_exact(fmaf(B0L, t, A0L)) * FAR_DIST;  // exact tail
        }
        g *= gr;
        sumL += inc;                                      // carried: 1 add
        float Tn = ex2a(-sumL);                           // off carried path
        float wi = Tp - Tn;
        prew += wi + EPS_W;
        pre[i+1] = prew;
        float wh = 0.5f * wi;
        r0 += fmaf(wh, tanha(fmaf(BcH0, t, AcH0)), wh);
        r1 += fmaf(wh, tanha(fmaf(BcH1, t, AcH1)), wh);
        r2 += fmaf(wh, tanha(fmaf(BcH2, t, AcH2)), wh);
        depth = fmaf(wi, t, depth);
        acc  += wi;
        Tp = Tn;
    }
    const float wsum = prew;

    if (3*NL <= out_size) {
        out[(long long)ray*3+0] = r0 + (1.0f - acc);
        out[(long long)ray*3+1] = r1 + (1.0f - acc);
        out[(long long)ray*3+2] = r2 + (1.0f - acc);
    }
    if (4*NL <= out_size) out[3*NL + ray] = depth;
    if (5*NL <= out_size) out[4*NL + ray] = acc;

    // -------- fused sampler + merge + fine render --------
    float fr0 = 0.f, fr1 = 0.f, fr2 = 0.f, fdep = 0.f, facc = 0.f;

    const float inv_wsum = rcpa(wsum);
    const float epsw_s   = EPS_W * wsum;   // degenerate-denominator threshold

    int   b = 0, k = 0;
    float tb    = NEARP;
    float preb  = 0.0f;                    // pre[b]
    float preb1 = pre[1];                  // pre[b+1]
    float preb2 = pre[2];                  // pre[b+2]
    float uk  = 0.0f;                      // current u
    float ukw = 0.0f;                      // u * wsum

    float pend = NEARP;                                   // pending sample
    float pdL  = densL_cheap(fmaf(B0L, NEARP, A0L));      // pipelined density
    float pc0  = tanha(fmaf(BcH0, NEARP, AcH0));          // pipelined colors
    float pc1  = tanha(fmaf(BcH1, NEARP, AcH1));
    float pc2  = tanha(fmaf(BcH2, NEARP, AcH2));

    float fsum = 0.0f;                     // fine optical depth (log2)
    float fTp  = 1.0f;

    #pragma unroll 2
    for (int it = 1; it < NS + NI; it++) {
        // value preb2 must take AFTER an advance: pre[(b+1)+2] = pre[b+3]
        int   bp = (b + 3 <= NS) ? (b + 3) : NS;
        float preload = pre[bp];

        // ---- branchless next-sample selection (unnormalized CDF) ----
        bool  imp  = (k < NI) && ((ukw < preb1) || (b == NS-1));
        float diff = preb1 - preb;
        bool  deg  = diff < epsw_s;
        float frnd = (ukw - preb) * rcpa(diff);
        float frd  = fmaf(-preb, inv_wsum, uk);           // (u - cdf0)/1
        float frac = deg ? frd : frnd;
        float dt   = (b < NS-1) ? STEP : 0.0f;
        float s_adv = tb + STEP;
        float s     = imp ? fmaf(frac, dt, tb) : s_adv;

        b     = imp ? b     : (b + 1);
        tb    = imp ? tb    : s_adv;
        preb  = imp ? preb  : preb1;
        preb1 = imp ? preb1 : preb2;
        preb2 = imp ? preb2 : preload;
        k    += imp ? 1 : 0;
        float un = (k == NI-1) ? 1.0f : (float)k * (1.0f/63.0f);
        uk    = imp ? un : uk;
        ukw   = imp ? un * wsum : ukw;

        // ---- render pending sample: carried chain is ONE fma (fsum) ----
        fsum = fmaf(pdL, s - pend, fsum);
        float Tn = ex2a(-fsum);                           // off carried path
        float wi = fTp - Tn;
        float wh = 0.5f * wi;
        fr0 += fmaf(wh, pc0, wh);
        fr1 += fmaf(wh, pc1, wh);
        fr2 += fmaf(wh, pc2, wh);
        fdep = fmaf(wi, pend, fdep);
        facc += wi;
        fTp = Tn;

        // ---- pipeline MUFUs for the new sample ----
        pend = s;
        pdL  = densL_cheap(fmaf(B0L, s, A0L));
        pc0  = tanha(fmaf(BcH0, s, AcH0));
        pc1  = tanha(fmaf(BcH1, s, AcH1));
        pc2  = tanha(fmaf(BcH2, s, AcH2));
    }
    // Last merged sample is ALWAYS t = FARP; dist = FAR_DIST needs exact tail.
    {
        float dL = densL_exact(fmaf(B0L, FARP, A0L));
        fsum = fmaf(dL, FAR_DIST, fsum);
        float Tn = ex2a(-fsum);
        float wi = fTp - Tn;
        float wh = 0.5f * wi;
        fr0 += fmaf(wh, pc0, wh);                         // pc* already at FARP
        fr1 += fmaf(wh, pc1, wh);
        fr2 += fmaf(wh, pc2, wh);
        fdep = fmaf(wi, FARP, fdep);
        facc += wi;
    }

    if (8*NL <= out_size) {
        out[5*NL + (long long)ray*3 + 0] = fr0 + (1.0f - facc);
        out[5*NL + (long long)ray*3 + 1] = fr1 + (1.0f - facc);
        out[5*NL + (long long)ray*3 + 2] = fr2 + (1.0f - facc);
    }
    if (9*NL  <= out_size) out[8*NL + ray] = fdep;
    if (10*NL <= out_size) out[9*NL + ray] = facc;
}

extern "C" void kernel_launch(void* const* d_in, const int* in_sizes, int n_in,
                              void* d_out, int out_size)
{
    const float* Wd = nullptr;
    const float* Wc = nullptr;
    for (int i = 0; i < n_in; i++) {
        if (in_sizes[i] == 3) Wd = (const float*)d_in[i];
        else if (in_sizes[i] == 9) Wc = (const float*)d_in[i];
    }
    int N = (out_size % 10 == 0) ? (out_size / 10) : (in_sizes[0] / 3);

    const float* ro = nullptr;
    const float* rd = nullptr;
    for (int i = 0; i < n_in; i++) {
        if (in_sizes[i] == 3 * N && in_sizes[i] > 9) {
            if (!ro) ro = (const float*)d_in[i];
            else if (!rd) { rd = (const float*)d_in[i]; break; }
        }
    }
    if (!ro || !rd) { ro = (const float*)d_in[0]; rd = (const float*)d_in[1]; }
    if (!Wd) Wd = (const float*)d_in[3];
    if (!Wc) Wc = (const float*)d_in[4];

    float* out = (float*)d_out;
    const int threads = 128;
    const int blocks  = (N + threads - 1) / threads;
    volume_render_kernel<<<blocks, threads>>>(ro, rd, Wd, Wc, out,
                                              N, (long long)out_size);
}

// round 13
// speedup vs baseline: 3.7234x; 1.0928x over previous
#include <cuda_runtime.h>
#include <stdint.h>

// VolumeRenderer: two-pass NeRF. One thread per ray.
// R13: minimized sampler state machine — no k/uk counters (counting-argument
// elimination), predicated ukw += wsum/63, shared num for both frac paths,
// 2-register pre[] rotation (post-update pnext load), dt reuses last-bin
// predicate. Coarse acc derived as wsum - 64*EPS_W.

constexpr int NS = 64;
constexpr int NI = 64;
constexpr float NEARP = 2.0f;
constexpr float FARP  = 6.0f;
constexpr float EPS_W = 1e-5f;
constexpr float FAR_DIST = 1e10f;
constexpr float LOG2E = 1.44269504088896340736f;

__device__ __forceinline__ float ex2a(float x){ float y; asm("ex2.approx.f32 %0,%1;":"=f"(y):"f"(x)); return y; }
__device__ __forceinline__ float lg2a(float x){ float y; asm("lg2.approx.f32 %0,%1;":"=f"(y):"f"(x)); return y; }
__device__ __forceinline__ float tanha(float x){ float y; asm("tanh.approx.f32 %0,%1;":"=f"(y):"f"(x)); return y; }
__device__ __forceinline__ float rcpa(float x){ float y; asm("rcp.approx.f32 %0,%1;":"=f"(y):"f"(x)); return y; }

// Cheap softplus*log2e (interior samples, dist <= ~4).
__device__ __forceinline__ float densL_cheap(float xL) {
    return lg2a(1.0f + ex2a(xL));
}
// Tail-preserving softplus*log2e — only where dist = FAR_DIST (R1 bug).
__device__ __forceinline__ float densL_exact(float xL) {
    float e = ex2a(-fabsf(xL));
    float lsmall = (e * LOG2E) * fmaf(e, fmaf(e, 0.33333334f, -0.5f), 1.0f);
    float lbig   = lg2a(1.0f + e);
    float l = (e < 0.03f) ? lsmall : lbig;
    return fmaxf(xL, 0.0f) + l;
}

__global__ __launch_bounds__(128)
void volume_render_kernel(const float* __restrict__ ro_g,
                          const float* __restrict__ rd_g,
                          const float* __restrict__ Wd_g,
                          const float* __restrict__ Wc_g,
                          float* __restrict__ out,
                          int N, long long out_size)
{
    const int ray = blockIdx.x * blockDim.x + threadIdx.x;
    if (ray >= N) return;

    const long long NL = (long long)N;

    const float ro0 = ro_g[ray*3+0], ro1 = ro_g[ray*3+1], ro2 = ro_g[ray*3+2];
    const float rd0 = rd_g[ray*3+0], rd1 = rd_g[ray*3+1], rd2 = rd_g[ray*3+2];

    const float wd0 = __ldg(Wd_g+0), wd1 = __ldg(Wd_g+1), wd2 = __ldg(Wd_g+2);

    const float A0L = (ro0*wd0 + ro1*wd1 + ro2*wd2) * LOG2E;
    const float B0L = (rd0*wd0 + rd1*wd1 + rd2*wd2) * LOG2E;

    float AcH0, AcH1, AcH2, BcH0, BcH1, BcH2;
    {
        float w00=__ldg(Wc_g+0), w01=__ldg(Wc_g+1), w02=__ldg(Wc_g+2);
        float w10=__ldg(Wc_g+3), w11=__ldg(Wc_g+4), w12=__ldg(Wc_g+5);
        float w20=__ldg(Wc_g+6), w21=__ldg(Wc_g+7), w22=__ldg(Wc_g+8);
        AcH0 = 0.5f*(ro0*w00 + ro1*w10 + ro2*w20);
        AcH1 = 0.5f*(ro0*w01 + ro1*w11 + ro2*w21);
        AcH2 = 0.5f*(ro0*w02 + ro1*w12 + ro2*w22);
        BcH0 = 0.5f*(rd0*w00 + rd1*w10 + rd2*w20);
        BcH1 = 0.5f*(rd0*w01 + rd1*w11 + rd2*w21);
        BcH2 = 0.5f*(rd0*w02 + rd1*w12 + rd2*w22);
    }

    const float STEP = (FARP - NEARP) / 63.0f;

    // -------- coarse pass: geometric density, log-space transmittance --------
    float pre[NS+1];                       // prefix sums of (w_i + EPS_W)
    pre[0] = 0.0f;
    float prew = 0.0f;
    float sumL = 0.0f;                     // optical depth (log2 space)
    float Tp   = 1.0f;
    float r0 = 0.f, r1 = 0.f, r2 = 0.f, depth = 0.f;

    float g = ex2a(fmaf(B0L, NEARP, A0L));     // 2^(xL) geometric on the grid
    const float gr = ex2a(B0L * STEP);

    #pragma unroll
    for (int i = 0; i < NS; i++) {
        const float t = NEARP + STEP * (float)i;          // constant-folded
        float inc;
        if (i < NS-1) {
            inc = lg2a(1.0f + g) * STEP;
        } else {
            inc = densL_exact(fmaf(B0L, t, A0L)) * FAR_DIST;
        }
        g *= gr;
        sumL += inc;
        float Tn = ex2a(-sumL);                           // off carried path
        float wi = Tp - Tn;
        prew += wi + EPS_W;
        pre[i+1] = prew;
        float wh = 0.5f * wi;
        r0 += fmaf(wh, tanha(fmaf(BcH0, t, AcH0)), wh);
        r1 += fmaf(wh, tanha(fmaf(BcH1, t, AcH1)), wh);
        r2 += fmaf(wh, tanha(fmaf(BcH2, t, AcH2)), wh);
        depth = fmaf(wi, t, depth);
        Tp = Tn;
    }
    const float wsum = prew;
    const float acc  = wsum - (float)NS * EPS_W;          // = sum(wi)

    if (3*NL <= out_size) {
        out[(long long)ray*3+0] = r0 + (1.0f - acc);
        out[(long long)ray*3+1] = r1 + (1.0f - acc);
        out[(long long)ray*3+2] = r2 + (1.0f - acc);
    }
    if (4*NL <= out_size) out[3*NL + ray] = depth;
    if (5*NL <= out_size) out[4*NL + ray] = acc;

    // -------- fused sampler + merge + fine render (minimized state) --------
    float fr0 = 0.f, fr1 = 0.f, fr2 = 0.f, fdep = 0.f, facc = 0.f;

    const float inv_wsum = rcpa(wsum);
    const float epsw_s   = EPS_W * wsum;
    const float dws      = wsum * (1.0f/63.0f);   // ukw increment per imp

    int   b = 0;
    float tb    = NEARP;
    float preb  = 0.0f;                    // pre[b]
    float preb1 = pre[1];                  // pre[b+1]
    float pnext = pre[2];                  // pre[b+2], staged one iter ahead
    float ukw   = 0.0f;                    // u_k * wsum (approx ladder)

    float pend = NEARP;
    float pdL  = densL_cheap(fmaf(B0L, NEARP, A0L));
    float pc0  = tanha(fmaf(BcH0, NEARP, AcH0));
    float pc1  = tanha(fmaf(BcH1, NEARP, AcH1));
    float pc2  = tanha(fmaf(BcH2, NEARP, AcH2));

    float fsum = 0.0f;
    float fTp  = 1.0f;

    #pragma unroll 2
    for (int it = 1; it < NS + NI; it++) {
        // ---- branchless selection (no k/uk counters; see counting argument) ----
        bool  last = (b == NS-1);
        bool  imp  = (ukw < preb1) || last;
        float diff = preb1 - preb;
        float num  = ukw - preb;
        float frac = (diff < epsw_s) ? (num * inv_wsum) : (num * rcpa(diff));
        float dt   = last ? 0.0f : STEP;
        float s_adv = tb + STEP;
        float s     = imp ? fmaf(frac, dt, tb) : s_adv;

        ukw  = imp ? (ukw + dws) : ukw;     // predicated ladder advance
        b    = imp ? b    : (b + 1);
        tb   = imp ? tb   : s_adv;
        preb = imp ? preb : preb1;
        preb1= imp ? preb1: pnext;
        {   // stage pre[b+2] for the NEXT potential advance (b already updated)
            int bp = (b + 2 <= NS) ? (b + 2) : NS;
            pnext = pre[bp];
        }

        // ---- render pending sample: carried chain is one FMA (fsum) ----
        fsum = fmaf(pdL, s - pend, fsum);
        float Tn = ex2a(-fsum);
        float wi = fTp - Tn;
        float wh = 0.5f * wi;
        fr0 += fmaf(wh, pc0, wh);
        fr1 += fmaf(wh, pc1, wh);
        fr2 += fmaf(wh, pc2, wh);
        fdep = fmaf(wi, pend, fdep);
        facc += wi;
        fTp = Tn;

        // ---- pipeline MUFUs for the new sample ----
        pend = s;
        pdL  = densL_cheap(fmaf(B0L, s, A0L));
        pc0  = tanha(fmaf(BcH0, s, AcH0));
        pc1  = tanha(fmaf(BcH1, s, AcH1));
        pc2  = tanha(fmaf(BcH2, s, AcH2));
    }
    // Last merged sample (pend = t63): dist = FAR_DIST, exact density tail.
    {
        float dL = densL_exact(fmaf(B0L, pend, A0L));
        fsum = fmaf(dL, FAR_DIST, fsum);
        float Tn = ex2a(-fsum);
        float wi = fTp - Tn;
        float wh = 0.5f * wi;
        fr0 += fmaf(wh, pc0, wh);                 // pc* already at pend
        fr1 += fmaf(wh, pc1, wh);
        fr2 += fmaf(wh, pc2, wh);
        fdep = fmaf(wi, pend, fdep);
        facc += wi;
    }

    if (8*NL <= out_size) {
        out[5*NL + (long long)ray*3 + 0] = fr0 + (1.0f - facc);
        out[5*NL + (long long)ray*3 + 1] = fr1 + (1.0f - facc);
        out[5*NL + (long long)ray*3 + 2] = fr2 + (1.0f - facc);
    }
    if (9*NL  <= out_size) out[8*NL + ray] = fdep;
    if (10*NL <= out_size) out[9*NL + ray] = facc;
}

extern "C" void kernel_launch(void* const* d_in, const int* in_sizes, int n_in,
                              void* d_out, int out_size)
{
    const float* Wd = nullptr;
    const float* Wc = nullptr;
    for (int i = 0; i < n_in; i++) {
        if (in_sizes[i] == 3) Wd = (const float*)d_in[i];
        else if (in_sizes[i] == 9) Wc = (const float*)d_in[i];
    }
    int N = (out_size % 10 == 0) ? (out_size / 10) : (in_sizes[0] / 3);

    const float* ro = nullptr;
    const float* rd = nullptr;
    for (int i = 0; i < n_in; i++) {
        if (in_sizes[i] == 3 * N && in_sizes[i] > 9) {
            if (!ro) ro = (const float*)d_in[i];
            else if (!rd) { rd = (const float*)d_in[i]; break; }
        }
    }
    if (!ro || !rd) { ro = (const float*)d_in[0]; rd = (const float*)d_in[1]; }
    if (!Wd) Wd = (const float*)d_in[3];
    if (!Wc) Wc = (const float*)d_in[4];

    float* out = (float*)d_out;
    const int threads = 128;
    const int blocks  = (N + threads - 1) / threads;
    volume_render_kernel<<<blocks, threads>>>(ro, rd, Wd, Wc, out,
                                              N, (long long)out_size);
}